// round 11
// baseline (speedup 1.0000x reference)
#include <cuda_runtime.h>
#include <math.h>

#define SPOS 576      // B*Ho*Wo = 4*12*12
#define CDIM 288      // KH*KW*Fin
#define FDIM 32
#define ODIM 16
#define CBLK 8
#define STILE 64
#define NST  9        // SPOS/STILE
#define NBLK (CDIM/CBLK)   // 36

typedef unsigned long long u64;

// Scratch (no allocations allowed)
// patches re-laid out for direct register loads:
//   g_patchR[ ((c*9 + st)*32 + lane)*16 + si*8 + i ],  s = st*64 + 2*lane + si
__device__ float  g_patchR[(size_t)CDIM * NST * 32 * 16];   // 5.3 MB
__device__ float  g_agreeT[(size_t)FDIM * CDIM * SPOS];     // [f][c][s] 21 MB
__device__ float2 g_den   [(size_t)CDIM * SPOS];            // (max, 1/sum) per (c,s)

__device__ __forceinline__ void fma2(u64& d, u64 a, u64 b) {
    asm("fma.rn.f32x2 %0, %1, %2, %0;" : "+l"(d) : "l"(a), "l"(b));
}
__device__ __forceinline__ float2 u2f(u64 v) {
    float2 f; asm("mov.b64 {%0,%1}, %2;" : "=f"(f.x), "=f"(f.y) : "l"(v)); return f;
}
__device__ __forceinline__ u64 f2u(float x, float y) {
    u64 v; asm("mov.b64 %0, {%1,%2};" : "=l"(v) : "f"(x), "f"(y)); return v;
}

// ---------------------------------------------------------------------------
// K0: im2col into the register-load-friendly layout.
// ---------------------------------------------------------------------------
__global__ void k_extract(const float* __restrict__ x) {
    int t = blockIdx.x * blockDim.x + threadIdx.x;
    if (t >= CDIM * SPOS) return;
    int s = t % SPOS, c = t / SPOS;
    int w = s % 12, h = (s / 12) % 12, b = s / 144;
    int fin = c & 31, kw = (c >> 5) % 3, kh = c / 96;
    const float* src = x + (size_t)(((b * 14 + h + kh) * 14 + (w + kw)) * 32 + fin) * 8;
    float4 v0 = *(const float4*)src;
    float4 v1 = *(const float4*)(src + 4);
    int st = s >> 6, l = (s & 63) >> 1, si = s & 1;
    float* dst = g_patchR + (((size_t)c * NST + st) * 32 + l) * 16 + si * 8;
    *(float4*)dst       = v0;
    *(float4*)(dst + 4) = v1;
}

// ---------------------------------------------------------------------------
// K1: per (f, 64-s tile), 256 thr = 4 c-groups x 2 o-halves; warp-private W;
// P loaded straight to registers (no smem staging, no block barriers).
// ---------------------------------------------------------------------------
__global__ void __launch_bounds__(256) k_phase1(const float* __restrict__ Wg) {
    __shared__ __align__(16) float Wsm[8][1024];   // 4KB per warp
    __shared__ float Cent[ODIM][STILE];
    __shared__ float Fac[STILE];

    const int f = blockIdx.x, st = blockIdx.y;
    const int tid = threadIdx.x, warp = tid >> 5, lane = tid & 31;
    const int g = warp >> 1, h = warp & 1;
    const int sbase = st * STILE;
    const float* Wf = Wg + (size_t)f * CDIM * 128;
    const float4* Wf4 = (const float4*)Wf;
    float* Wp = Wsm[warp];

    for (int k = tid; k < ODIM * STILE; k += 256) ((float*)Cent)[k] = 0.f;
    __syncthreads();

    const u64* Pl = (const u64*)(g_patchR + ((size_t)st * 32 + lane) * 16);
    // c stride in this layout: 9*32*16 floats = 2304 u64
    u64 acc[8][2];
    #pragma unroll
    for (int o = 0; o < 8; o++) { acc[o][0] = 0ULL; acc[o][1] = 0ULL; }

    // ---------------- pass 1: centroid ----------------
    for (int blk = g; blk < NBLK; blk += 4) {
        int c0 = blk * CBLK;
        __syncwarp();
        #pragma unroll
        for (int k = 0; k < 4; k++) {          // warp's o-half of W chunk: 2KB
            int t = lane + 32 * k;
            int cc = t >> 4, r = t & 15, o = r >> 1, q = r & 1;
            ((float4*)Wp)[t] = Wf4[((c0 + cc) * 16 + h * 8 + o) * 2 + q];
        }
        __syncwarp();
        #pragma unroll
        for (int cc = 0; cc < CBLK; cc++) {
            const u64* Pc = Pl + (size_t)(c0 + cc) * 2304;
            ulonglong2 qa0 = *(const ulonglong2*)(Pc);
            ulonglong2 qa1 = *(const ulonglong2*)(Pc + 2);
            ulonglong2 qb0 = *(const ulonglong2*)(Pc + 4);
            ulonglong2 qb1 = *(const ulonglong2*)(Pc + 6);
            #pragma unroll
            for (int o = 0; o < 8; o++) {
                const ulonglong2* wr = (const ulonglong2*)(Wp + cc * 64 + o * 8);
                ulonglong2 w0 = wr[0], w1 = wr[1];
                fma2(acc[o][0], w0.x, qa0.x); fma2(acc[o][0], w0.y, qa0.y);
                fma2(acc[o][0], w1.x, qa1.x); fma2(acc[o][0], w1.y, qa1.y);
                fma2(acc[o][1], w0.x, qb0.x); fma2(acc[o][1], w0.y, qb0.y);
                fma2(acc[o][1], w1.x, qb1.x); fma2(acc[o][1], w1.y, qb1.y);
            }
        }
    }
    #pragma unroll
    for (int o = 0; o < 8; o++) {
        float2 v0 = u2f(acc[o][0]), v1 = u2f(acc[o][1]);
        atomicAdd(&Cent[h * 8 + o][2 * lane],     v0.x + v0.y);
        atomicAdd(&Cent[h * 8 + o][2 * lane + 1], v1.x + v1.y);
    }
    __syncthreads();
    if (tid < STILE) {
        const float inv32 = 1.f / 32.f;
        float sn = 0.f;
        #pragma unroll
        for (int o = 0; o < 16; o++) { float v = Cent[o][tid] * inv32; sn += v * v; }
        Fac[tid] = (sn / ((1.f + sn) * sqrtf(sn + 1e-7f))) * inv32;  // fold /32
    }
    __syncthreads();
    float fw0 = Fac[2 * lane], fw1 = Fac[2 * lane + 1];
    float2 o1[16];
    #pragma unroll
    for (int o = 0; o < 16; o++) {
        float2 cv = *(float2*)&Cent[o][2 * lane];
        o1[o] = make_float2(cv.x * fw0, cv.y * fw1);
    }

    // ---------------- pass 2: agreement (warp loads FULL W chunk) ----------
    for (int blk = g; blk < NBLK; blk += 4) {
        int c0 = blk * CBLK;
        __syncwarp();
        #pragma unroll
        for (int k = 0; k < 8; k++)            // full 4KB chunk, contiguous
            ((float4*)Wp)[lane + 32 * k] = Wf4[c0 * 32 + lane + 32 * k];
        __syncwarp();
        #pragma unroll
        for (int j = 0; j < 4; j++) {
            int cc = h * 4 + j;
            const u64* Pc = Pl + (size_t)(c0 + cc) * 2304;
            ulonglong2 qa0 = *(const ulonglong2*)(Pc);
            ulonglong2 qa1 = *(const ulonglong2*)(Pc + 2);
            ulonglong2 qb0 = *(const ulonglong2*)(Pc + 4);
            ulonglong2 qb1 = *(const ulonglong2*)(Pc + 6);
            u64 ag0 = 0ULL, ag1 = 0ULL;
            #pragma unroll
            for (int o = 0; o < 16; o++) {
                const ulonglong2* wr = (const ulonglong2*)(Wp + cc * 128 + o * 8);
                ulonglong2 w0 = wr[0], w1 = wr[1];
                u64 pr0 = 0ULL, pr1 = 0ULL;
                fma2(pr0, w0.x, qa0.x); fma2(pr0, w0.y, qa0.y);
                fma2(pr0, w1.x, qa1.x); fma2(pr0, w1.y, qa1.y);
                fma2(pr1, w0.x, qb0.x); fma2(pr1, w0.y, qb0.y);
                fma2(pr1, w1.x, qb1.x); fma2(pr1, w1.y, qb1.y);
                fma2(ag0, f2u(o1[o].x, o1[o].x), pr0);
                fma2(ag1, f2u(o1[o].y, o1[o].y), pr1);
            }
            float2 r0 = u2f(ag0), r1 = u2f(ag1);
            *(float2*)&g_agreeT[((size_t)f * CDIM + c0 + cc) * SPOS + sbase + 2 * lane] =
                make_float2(r0.x + r0.y, r1.x + r1.y);
        }
    }
}

// ---------------------------------------------------------------------------
// K2: per (c,s): softmax denominator over f -> (max, 1/sum). cc reconstructed
// inline in K3; saves the 21MB cc tensor round trip.
// ---------------------------------------------------------------------------
__global__ void k_den() {
    int j = blockIdx.x * blockDim.x + threadIdx.x;
    if (j >= CDIM * SPOS) return;
    float v[32];
    float mx = -1e30f;
    #pragma unroll
    for (int ff = 0; ff < 32; ff++) {
        v[ff] = g_agreeT[(size_t)ff * (CDIM * SPOS) + j];
        mx = fmaxf(mx, v[ff]);
    }
    float sum = 0.f;
    #pragma unroll
    for (int ff = 0; ff < 32; ff++) sum += __expf(v[ff] - mx);
    g_den[j] = make_float2(mx, 1.f / sum);
}

// ---------------------------------------------------------------------------
// K3: centroid2 = sum_c cc * preds ; squash ; out[s][f][o]
// ---------------------------------------------------------------------------
__global__ void __launch_bounds__(256) k_phase3(const float* __restrict__ Wg,
                                                float* __restrict__ out) {
    __shared__ __align__(16) float Wsm[8][1024];
    __shared__ float Cent[ODIM][STILE];
    __shared__ float Fac[STILE];

    const int f = blockIdx.x, st = blockIdx.y;
    const int tid = threadIdx.x, warp = tid >> 5, lane = tid & 31;
    const int g = warp >> 1, h = warp & 1;
    const int sbase = st * STILE;
    const float* Wf = Wg + (size_t)f * CDIM * 128;
    const float4* Wf4 = (const float4*)Wf;
    float* Wp = Wsm[warp];

    for (int k = tid; k < ODIM * STILE; k += 256) ((float*)Cent)[k] = 0.f;
    __syncthreads();

    const u64* Pl = (const u64*)(g_patchR + ((size_t)st * 32 + lane) * 16);
    const float* agf = g_agreeT + (size_t)f * (CDIM * SPOS);

    u64 acc[8][2];
    #pragma unroll
    for (int o = 0; o < 8; o++) { acc[o][0] = 0ULL; acc[o][1] = 0ULL; }

    for (int blk = g; blk < NBLK; blk += 4) {
        int c0 = blk * CBLK;
        __syncwarp();
        #pragma unroll
        for (int k = 0; k < 4; k++) {
            int t = lane + 32 * k;
            int cc = t >> 4, r = t & 15, o = r >> 1, q = r & 1;
            ((float4*)Wp)[t] = Wf4[((c0 + cc) * 16 + h * 8 + o) * 2 + q];
        }
        __syncwarp();
        #pragma unroll
        for (int cc = 0; cc < CBLK; cc++) {
            // routing coefficient, reconstructed inline
            float2 ag = *(const float2*)(agf + (size_t)(c0 + cc) * SPOS + sbase + 2 * lane);
            float4 dv = *(const float4*)&g_den[(size_t)(c0 + cc) * SPOS + sbase + 2 * lane];
            float cx = __expf(ag.x - dv.x) * dv.y;
            float cy = __expf(ag.y - dv.z) * dv.w;
            u64 cda = f2u(cx, cx), cdb = f2u(cy, cy);

            const u64* Pc = Pl + (size_t)(c0 + cc) * 2304;
            ulonglong2 qa0 = *(const ulonglong2*)(Pc);
            ulonglong2 qa1 = *(const ulonglong2*)(Pc + 2);
            ulonglong2 qb0 = *(const ulonglong2*)(Pc + 4);
            ulonglong2 qb1 = *(const ulonglong2*)(Pc + 6);
            #pragma unroll
            for (int o = 0; o < 8; o++) {
                const ulonglong2* wr = (const ulonglong2*)(Wp + cc * 64 + o * 8);
                ulonglong2 w0 = wr[0], w1 = wr[1];
                u64 pr0 = 0ULL, pr1 = 0ULL;
                fma2(pr0, w0.x, qa0.x); fma2(pr0, w0.y, qa0.y);
                fma2(pr0, w1.x, qa1.x); fma2(pr0, w1.y, qa1.y);
                fma2(pr1, w0.x, qb0.x); fma2(pr1, w0.y, qb0.y);
                fma2(pr1, w1.x, qb1.x); fma2(pr1, w1.y, qb1.y);
                fma2(acc[o][0], cda, pr0);
                fma2(acc[o][1], cdb, pr1);
            }
        }
    }
    #pragma unroll
    for (int o = 0; o < 8; o++) {
        float2 v0 = u2f(acc[o][0]), v1 = u2f(acc[o][1]);
        atomicAdd(&Cent[h * 8 + o][2 * lane],     v0.x + v0.y);
        atomicAdd(&Cent[h * 8 + o][2 * lane + 1], v1.x + v1.y);
    }
    __syncthreads();
    if (tid < STILE) {
        float sn = 0.f;
        #pragma unroll
        for (int o = 0; o < 16; o++) { float v = Cent[o][tid]; sn += v * v; }
        Fac[tid] = sn / ((1.f + sn) * sqrtf(sn + 1e-7f));
    }
    __syncthreads();
    {
        int s = tid >> 2, oq = tid & 3;    // 64 s x 4 o-quads = 256
        float fs = Fac[s];
        float4 r;
        r.x = Cent[oq * 4 + 0][s] * fs;
        r.y = Cent[oq * 4 + 1][s] * fs;
        r.z = Cent[oq * 4 + 2][s] * fs;
        r.w = Cent[oq * 4 + 3][s] * fs;
        *(float4*)(out + ((size_t)(sbase + s) * FDIM + f) * ODIM + oq * 4) = r;
    }
}

// ---------------------------------------------------------------------------
extern "C" void kernel_launch(void* const* d_in, const int* in_sizes, int n_in,
                              void* d_out, int out_size) {
    const float* x  = (const float*)d_in[0];
    const float* Wg = (const float*)d_in[1];
    if (n_in >= 2 && in_sizes[0] == 1179648) { const float* t = x; x = Wg; Wg = t; }
    float* out = (float*)d_out;

    k_extract<<<(CDIM * SPOS + 255) / 256, 256>>>(x);
    dim3 g(FDIM, NST);   // (32, 9) = 288 CTAs, 2 CTAs/SM
    k_phase1<<<g, 256>>>(Wg);
    k_den<<<(CDIM * SPOS + 255) / 256, 256>>>();
    k_phase3<<<g, 256>>>(Wg, out);
}

// round 15
// speedup vs baseline: 1.1795x; 1.1795x over previous
#include <cuda_runtime.h>
#include <math.h>

#define SPOS 576      // B*Ho*Wo = 4*12*12
#define CDIM 288      // KH*KW*Fin
#define FDIM 32
#define ODIM 16
#define CBLK 8
#define STILE 64
#define NST  9        // SPOS/STILE
#define NBLK (CDIM/CBLK)   // 36

typedef unsigned long long u64;

// Scratch (no allocations allowed)
// P in i-pair-major layout: g_patchP[(c*4 + k)*SPOS + s] = (x_i2k, x_i2k+1)
__device__ u64    g_patchP[(size_t)CDIM * 4 * SPOS];        // 5.3 MB
__device__ float  g_agreeT[(size_t)FDIM * CDIM * SPOS];     // [f][c][s] 21 MB
__device__ float2 g_den   [(size_t)CDIM * SPOS];            // (max, 1/sum)

// dynamic smem layout (floats): 4 groups x (W 1024 + P 4096), Cent, Fac
#define OFF_W    0
#define OFF_P    4096
#define OFF_CENT 20480
#define OFF_FAC  21504
#define SMEM_BYTES ((21504 + 64) * 4)   // 86272 B -> 2 CTAs/SM

__device__ __forceinline__ void fma2(u64& d, u64 a, u64 b) {
    asm("fma.rn.f32x2 %0, %1, %2, %0;" : "+l"(d) : "l"(a), "l"(b));
}
__device__ __forceinline__ float2 u2f(u64 v) {
    float2 f; asm("mov.b64 {%0,%1}, %2;" : "=f"(f.x), "=f"(f.y) : "l"(v)); return f;
}
__device__ __forceinline__ u64 f2u(float x, float y) {
    u64 v; asm("mov.b64 %0, {%1,%2};" : "=l"(v) : "f"(x), "f"(y)); return v;
}

// ---------------------------------------------------------------------------
// K0: im2col into i-pair-major layout (4 coalesced u64 stores per thread).
// ---------------------------------------------------------------------------
__global__ void k_extract(const float* __restrict__ x) {
    int t = blockIdx.x * blockDim.x + threadIdx.x;
    if (t >= CDIM * SPOS) return;
    int s = t % SPOS, c = t / SPOS;
    int w = s % 12, h = (s / 12) % 12, b = s / 144;
    int fin = c & 31, kw = (c >> 5) % 3, kh = c / 96;
    const float* src = x + (size_t)(((b * 14 + h + kh) * 14 + (w + kw)) * 32 + fin) * 8;
    float4 v0 = *(const float4*)src;
    float4 v1 = *(const float4*)(src + 4);
    u64* dst = g_patchP + (size_t)c * 4 * SPOS + s;
    dst[0 * SPOS] = f2u(v0.x, v0.y);
    dst[1 * SPOS] = f2u(v0.z, v0.w);
    dst[2 * SPOS] = f2u(v1.x, v1.y);
    dst[3 * SPOS] = f2u(v1.z, v1.w);
}

// group loader (64 threads): W chunk 4KB + P tile (32 u64-rows x 64 s = 16KB)
// P tile row = 64 u64 = 32 float4; 32 rows -> 1024 float4 total.
__device__ __forceinline__ void load_tiles(float* Wp, u64* Pt,
                                           const float4* Wf4, int c0,
                                           int sbase, int wtid) {
    #pragma unroll
    for (int k = 0; k < 4; k++)
        ((float4*)Wp)[wtid + 64 * k] = Wf4[c0 * 32 + wtid + 64 * k];
    #pragma unroll
    for (int k = 0; k < 16; k++) {
        int flat = wtid + 64 * k;           // over 1024 float4
        int row = flat >> 5, q = flat & 31; // 32 float4 per row
        ((float4*)Pt)[row * 32 + q] =
            ((const float4*)(g_patchP + (size_t)(c0 * 4 + row) * SPOS + sbase))[q];
    }
}

// ---------------------------------------------------------------------------
// K1: per (f, 64-s tile), 256 thr = 4 c-groups x 2 o-halves; conflict-free P.
// ---------------------------------------------------------------------------
__global__ void __launch_bounds__(256, 2) k_phase1(const float* __restrict__ Wg) {
    extern __shared__ float sm[];
    const int f = blockIdx.x, st = blockIdx.y;
    const int tid = threadIdx.x, warp = tid >> 5, lane = tid & 31;
    const int g = warp >> 1, h = warp & 1, wtid = tid & 63;
    const int sbase = st * STILE;
    float* Wp   = sm + OFF_W + g * 1024;
    u64*   Pt   = (u64*)(sm + OFF_P + g * 4096);
    float* Cent = sm + OFF_CENT;
    float* Fac  = sm + OFF_FAC;
    const float4* Wf4 = (const float4*)(Wg + (size_t)f * CDIM * 128);

    for (int k = tid; k < ODIM * STILE; k += 256) Cent[k] = 0.f;
    __syncthreads();

    u64 acc[8][2];
    #pragma unroll
    for (int o = 0; o < 8; o++) { acc[o][0] = 0ULL; acc[o][1] = 0ULL; }

    // ---------------- pass 1: centroid ----------------
    for (int blk = g; blk < NBLK; blk += 4) {
        int c0 = blk * CBLK;
        asm volatile("bar.sync %0, 64;" :: "r"(g + 1) : "memory");
        load_tiles(Wp, Pt, Wf4, c0, sbase, wtid);
        asm volatile("bar.sync %0, 64;" :: "r"(g + 1) : "memory");
        #pragma unroll
        for (int cc = 0; cc < CBLK; cc++) {
            const u64* Pc = Pt + cc * 256;   // 4 k-rows of 64 u64
            ulonglong2 q0 = *(const ulonglong2*)(Pc +   0 + 2 * lane);
            ulonglong2 q1 = *(const ulonglong2*)(Pc +  64 + 2 * lane);
            ulonglong2 q2 = *(const ulonglong2*)(Pc + 128 + 2 * lane);
            ulonglong2 q3 = *(const ulonglong2*)(Pc + 192 + 2 * lane);
            #pragma unroll
            for (int o = 0; o < 8; o++) {
                const ulonglong2* wr = (const ulonglong2*)(Wp + (cc * 16 + h * 8 + o) * 8);
                ulonglong2 w0 = wr[0], w1 = wr[1];
                fma2(acc[o][0], w0.x, q0.x); fma2(acc[o][0], w0.y, q1.x);
                fma2(acc[o][0], w1.x, q2.x); fma2(acc[o][0], w1.y, q3.x);
                fma2(acc[o][1], w0.x, q0.y); fma2(acc[o][1], w0.y, q1.y);
                fma2(acc[o][1], w1.x, q2.y); fma2(acc[o][1], w1.y, q3.y);
            }
        }
    }
    #pragma unroll
    for (int o = 0; o < 8; o++) {
        float2 v0 = u2f(acc[o][0]), v1 = u2f(acc[o][1]);
        atomicAdd(&Cent[(h * 8 + o) * STILE + 2 * lane],     v0.x + v0.y);
        atomicAdd(&Cent[(h * 8 + o) * STILE + 2 * lane + 1], v1.x + v1.y);
    }
    __syncthreads();
    if (tid < STILE) {
        const float inv32 = 1.f / 32.f;
        float sn = 0.f;
        #pragma unroll
        for (int o = 0; o < 16; o++) { float v = Cent[o * STILE + tid] * inv32; sn += v * v; }
        Fac[tid] = (sn / ((1.f + sn) * sqrtf(sn + 1e-7f))) * inv32;  // fold /32
    }
    __syncthreads();
    float fw0 = Fac[2 * lane], fw1 = Fac[2 * lane + 1];
    float2 o1[16];
    #pragma unroll
    for (int o = 0; o < 16; o++) {
        float2 cv = *(float2*)&Cent[o * STILE + 2 * lane];
        o1[o] = make_float2(cv.x * fw0, cv.y * fw1);
    }

    // ---------------- pass 2: agreement ----------------
    for (int blk = g; blk < NBLK; blk += 4) {
        int c0 = blk * CBLK;
        asm volatile("bar.sync %0, 64;" :: "r"(g + 1) : "memory");
        load_tiles(Wp, Pt, Wf4, c0, sbase, wtid);
        asm volatile("bar.sync %0, 64;" :: "r"(g + 1) : "memory");
        #pragma unroll
        for (int j = 0; j < 4; j++) {
            int cc = h * 4 + j;
            const u64* Pc = Pt + cc * 256;
            ulonglong2 q0 = *(const ulonglong2*)(Pc +   0 + 2 * lane);
            ulonglong2 q1 = *(const ulonglong2*)(Pc +  64 + 2 * lane);
            ulonglong2 q2 = *(const ulonglong2*)(Pc + 128 + 2 * lane);
            ulonglong2 q3 = *(const ulonglong2*)(Pc + 192 + 2 * lane);
            u64 ag0 = 0ULL, ag1 = 0ULL;
            #pragma unroll
            for (int o = 0; o < 16; o++) {
                const ulonglong2* wr = (const ulonglong2*)(Wp + (cc * 16 + o) * 8);
                ulonglong2 w0 = wr[0], w1 = wr[1];
                u64 pr0 = 0ULL, pr1 = 0ULL;
                fma2(pr0, w0.x, q0.x); fma2(pr0, w0.y, q1.x);
                fma2(pr0, w1.x, q2.x); fma2(pr0, w1.y, q3.x);
                fma2(pr1, w0.x, q0.y); fma2(pr1, w0.y, q1.y);
                fma2(pr1, w1.x, q2.y); fma2(pr1, w1.y, q3.y);
                fma2(ag0, f2u(o1[o].x, o1[o].x), pr0);
                fma2(ag1, f2u(o1[o].y, o1[o].y), pr1);
            }
            float2 r0 = u2f(ag0), r1 = u2f(ag1);
            *(float2*)&g_agreeT[((size_t)f * CDIM + c0 + cc) * SPOS + sbase + 2 * lane] =
                make_float2(r0.x + r0.y, r1.x + r1.y);
        }
    }
}

// ---------------------------------------------------------------------------
// K2: softmax denominator over f per (c,s): (max, 1/sum). cc rebuilt in K3.
// ---------------------------------------------------------------------------
__global__ void k_den() {
    int j = blockIdx.x * blockDim.x + threadIdx.x;
    if (j >= CDIM * SPOS) return;
    float v[32];
    float mx = -1e30f;
    #pragma unroll
    for (int ff = 0; ff < 32; ff++) {
        v[ff] = g_agreeT[(size_t)ff * (CDIM * SPOS) + j];
        mx = fmaxf(mx, v[ff]);
    }
    float sum = 0.f;
    #pragma unroll
    for (int ff = 0; ff < 32; ff++) sum += __expf(v[ff] - mx);
    g_den[j] = make_float2(mx, 1.f / sum);
}

// ---------------------------------------------------------------------------
// K3: centroid2 = sum_c cc * preds ; squash ; out[s][f][o]
// ---------------------------------------------------------------------------
__global__ void __launch_bounds__(256, 2) k_phase3(const float* __restrict__ Wg,
                                                   float* __restrict__ out) {
    extern __shared__ float sm[];
    const int f = blockIdx.x, st = blockIdx.y;
    const int tid = threadIdx.x, warp = tid >> 5, lane = tid & 31;
    const int g = warp >> 1, h = warp & 1, wtid = tid & 63;
    const int sbase = st * STILE;
    float* Wp   = sm + OFF_W + g * 1024;
    u64*   Pt   = (u64*)(sm + OFF_P + g * 4096);
    float* Cent = sm + OFF_CENT;
    float* Fac  = sm + OFF_FAC;
    const float4* Wf4 = (const float4*)(Wg + (size_t)f * CDIM * 128);
    const float* agf = g_agreeT + (size_t)f * (CDIM * SPOS);

    for (int k = tid; k < ODIM * STILE; k += 256) Cent[k] = 0.f;
    __syncthreads();

    u64 acc[8][2];
    #pragma unroll
    for (int o = 0; o < 8; o++) { acc[o][0] = 0ULL; acc[o][1] = 0ULL; }

    for (int blk = g; blk < NBLK; blk += 4) {
        int c0 = blk * CBLK;
        asm volatile("bar.sync %0, 64;" :: "r"(g + 1) : "memory");
        load_tiles(Wp, Pt, Wf4, c0, sbase, wtid);
        asm volatile("bar.sync %0, 64;" :: "r"(g + 1) : "memory");
        #pragma unroll
        for (int cc = 0; cc < CBLK; cc++) {
            // routing coefficient rebuilt inline: cc = exp(agr - max) / sum
            float2 ag = *(const float2*)(agf + (size_t)(c0 + cc) * SPOS + sbase + 2 * lane);
            float4 dv = *(const float4*)&g_den[(size_t)(c0 + cc) * SPOS + sbase + 2 * lane];
            float cx = __expf(ag.x - dv.x) * dv.y;
            float cy = __expf(ag.y - dv.z) * dv.w;
            u64 cda = f2u(cx, cx), cdb = f2u(cy, cy);

            const u64* Pc = Pt + cc * 256;
            ulonglong2 q0 = *(const ulonglong2*)(Pc +   0 + 2 * lane);
            ulonglong2 q1 = *(const ulonglong2*)(Pc +  64 + 2 * lane);
            ulonglong2 q2 = *(const ulonglong2*)(Pc + 128 + 2 * lane);
            ulonglong2 q3 = *(const ulonglong2*)(Pc + 192 + 2 * lane);
            #pragma unroll
            for (int o = 0; o < 8; o++) {
                const ulonglong2* wr = (const ulonglong2*)(Wp + (cc * 16 + h * 8 + o) * 8);
                ulonglong2 w0 = wr[0], w1 = wr[1];
                u64 pr0 = 0ULL, pr1 = 0ULL;
                fma2(pr0, w0.x, q0.x); fma2(pr0, w0.y, q1.x);
                fma2(pr0, w1.x, q2.x); fma2(pr0, w1.y, q3.x);
                fma2(pr1, w0.x, q0.y); fma2(pr1, w0.y, q1.y);
                fma2(pr1, w1.x, q2.y); fma2(pr1, w1.y, q3.y);
                fma2(acc[o][0], cda, pr0);
                fma2(acc[o][1], cdb, pr1);
            }
        }
    }
    #pragma unroll
    for (int o = 0; o < 8; o++) {
        float2 v0 = u2f(acc[o][0]), v1 = u2f(acc[o][1]);
        atomicAdd(&Cent[(h * 8 + o) * STILE + 2 * lane],     v0.x + v0.y);
        atomicAdd(&Cent[(h * 8 + o) * STILE + 2 * lane + 1], v1.x + v1.y);
    }
    __syncthreads();
    if (tid < STILE) {
        float sn = 0.f;
        #pragma unroll
        for (int o = 0; o < 16; o++) { float v = Cent[o * STILE + tid]; sn += v * v; }
        Fac[tid] = sn / ((1.f + sn) * sqrtf(sn + 1e-7f));
    }
    __syncthreads();
    {
        int s = tid >> 2, oq = tid & 3;    // 64 s x 4 o-quads = 256
        float fs = Fac[s];
        float4 r;
        r.x = Cent[(oq * 4 + 0) * STILE + s] * fs;
        r.y = Cent[(oq * 4 + 1) * STILE + s] * fs;
        r.z = Cent[(oq * 4 + 2) * STILE + s] * fs;
        r.w = Cent[(oq * 4 + 3) * STILE + s] * fs;
        *(float4*)(out + ((size_t)(sbase + s) * FDIM + f) * ODIM + oq * 4) = r;
    }
}

// ---------------------------------------------------------------------------
extern "C" void kernel_launch(void* const* d_in, const int* in_sizes, int n_in,
                              void* d_out, int out_size) {
    const float* x  = (const float*)d_in[0];
    const float* Wg = (const float*)d_in[1];
    if (n_in >= 2 && in_sizes[0] == 1179648) { const float* t = x; x = Wg; Wg = t; }
    float* out = (float*)d_out;

    cudaFuncSetAttribute(k_phase1, cudaFuncAttributeMaxDynamicSharedMemorySize, SMEM_BYTES);
    cudaFuncSetAttribute(k_phase3, cudaFuncAttributeMaxDynamicSharedMemorySize, SMEM_BYTES);

    k_extract<<<(CDIM * SPOS + 255) / 256, 256>>>(x);
    dim3 g(FDIM, NST);   // (32, 9) = 288 CTAs, 2 CTAs/SM
    k_phase1<<<g, 256, SMEM_BYTES>>>(Wg);
    k_den<<<(CDIM * SPOS + 255) / 256, 256>>>();
    k_phase3<<<g, 256, SMEM_BYTES>>>(Wg, out);
}

// round 16
// speedup vs baseline: 1.3035x; 1.1052x over previous
#include <cuda_runtime.h>
#include <math.h>

#define SPOS 576      // B*Ho*Wo = 4*12*12
#define CDIM 288      // KH*KW*Fin
#define FDIM 32
#define ODIM 16
#define STILE 64
#define NST  9        // SPOS/STILE
#define NBLK 36       // CDIM/8

typedef unsigned long long u64;

// Scratch (no allocations allowed)
// P in i-pair-major layout: g_patchP[(c*4 + k)*SPOS + s] = (x_i2k, x_i2k+1)
__device__ u64    g_patchP[(size_t)CDIM * 4 * SPOS];        // 5.3 MB
__device__ float  g_agreeT[(size_t)FDIM * CDIM * SPOS];     // [f][c][s] 21 MB
__device__ float2 g_den   [(size_t)CDIM * SPOS];            // (max, 1/sum)

__device__ __forceinline__ void fma2(u64& d, u64 a, u64 b) {
    asm("fma.rn.f32x2 %0, %1, %2, %0;" : "+l"(d) : "l"(a), "l"(b));
}
__device__ __forceinline__ float2 u2f(u64 v) {
    float2 f; asm("mov.b64 {%0,%1}, %2;" : "=f"(f.x), "=f"(f.y) : "l"(v)); return f;
}
__device__ __forceinline__ u64 f2u(float x, float y) {
    u64 v; asm("mov.b64 %0, {%1,%2};" : "=l"(v) : "f"(x), "f"(y)); return v;
}

// ---------------------------------------------------------------------------
// K0: im2col into i-pair-major layout (4 coalesced u64 stores per thread).
// ---------------------------------------------------------------------------
__global__ void k_extract(const float* __restrict__ x) {
    int t = blockIdx.x * blockDim.x + threadIdx.x;
    if (t >= CDIM * SPOS) return;
    int s = t % SPOS, c = t / SPOS;
    int w = s % 12, h = (s / 12) % 12, b = s / 144;
    int fin = c & 31, kw = (c >> 5) % 3, kh = c / 96;
    const float* src = x + (size_t)(((b * 14 + h + kh) * 14 + (w + kw)) * 32 + fin) * 8;
    float4 v0 = *(const float4*)src;
    float4 v1 = *(const float4*)(src + 4);
    u64* dst = g_patchP + (size_t)c * 4 * SPOS + s;
    dst[0 * SPOS] = f2u(v0.x, v0.y);
    dst[1 * SPOS] = f2u(v0.z, v0.w);
    dst[2 * SPOS] = f2u(v1.x, v1.y);
    dst[3 * SPOS] = f2u(v1.z, v1.w);
}

// ---------------------------------------------------------------------------
// K1: per (f, 64-s tile). 8 warps; warp w owns cc=w of each 8-c block,
// all 16 o, 64 s (2/lane). P direct LDG (pipelined), W double-buffered smem.
// ---------------------------------------------------------------------------
__global__ void __launch_bounds__(256, 2) k_phase1(const float* __restrict__ Wg) {
    __shared__ __align__(16) float Wb[2][1024];
    __shared__ float Part[8][ODIM * STILE];     // 32 KB
    __shared__ float Cent[ODIM * STILE];
    __shared__ float Fac[STILE];

    const int f = blockIdx.x, st = blockIdx.y;
    const int tid = threadIdx.x, w = tid >> 5, lane = tid & 31;
    const int sbase = st * STILE;
    const float4* Wf4 = (const float4*)(Wg + (size_t)f * CDIM * 128);
    const u64* Pw = g_patchP + (size_t)w * 4 * SPOS + sbase + 2 * lane;  // c=w

    ulonglong2 acc[16];
    #pragma unroll
    for (int o = 0; o < 16; o++) acc[o] = make_ulonglong2(0ULL, 0ULL);

    // ---------------- pass 1: centroid ----------------
    ((float4*)Wb[0])[tid] = Wf4[tid];
    ulonglong2 q0 = *(const ulonglong2*)(Pw);
    ulonglong2 q1 = *(const ulonglong2*)(Pw + SPOS);
    ulonglong2 q2 = *(const ulonglong2*)(Pw + 2 * SPOS);
    ulonglong2 q3 = *(const ulonglong2*)(Pw + 3 * SPOS);
    __syncthreads();

    for (int blk = 0; blk < NBLK; blk++) {
        int nb = (blk + 1 < NBLK) ? blk + 1 : 0;
        ((float4*)Wb[(blk + 1) & 1])[tid] = Wf4[nb * 256 + tid];
        const u64* Pn = g_patchP + ((size_t)(nb * 8 + w) * 4) * SPOS + sbase + 2 * lane;
        ulonglong2 n0 = *(const ulonglong2*)(Pn);
        ulonglong2 n1 = *(const ulonglong2*)(Pn + SPOS);
        ulonglong2 n2 = *(const ulonglong2*)(Pn + 2 * SPOS);
        ulonglong2 n3 = *(const ulonglong2*)(Pn + 3 * SPOS);

        const float* Wc = Wb[blk & 1] + w * 128;   // this warp's c: 16 o x 8 i
        #pragma unroll
        for (int o = 0; o < 16; o++) {
            const ulonglong2* wr = (const ulonglong2*)(Wc + o * 8);
            ulonglong2 w0 = wr[0], w1 = wr[1];
            fma2(acc[o].x, w0.x, q0.x); fma2(acc[o].x, w0.y, q1.x);
            fma2(acc[o].x, w1.x, q2.x); fma2(acc[o].x, w1.y, q3.x);
            fma2(acc[o].y, w0.x, q0.y); fma2(acc[o].y, w0.y, q1.y);
            fma2(acc[o].y, w1.x, q2.y); fma2(acc[o].y, w1.y, q3.y);
        }
        q0 = n0; q1 = n1; q2 = n2; q3 = n3;
        __syncthreads();
    }

    // cross-warp reduction (no atomics)
    #pragma unroll
    for (int o = 0; o < 16; o++) {
        float2 v0 = u2f(acc[o].x), v1 = u2f(acc[o].y);
        Part[w][o * STILE + 2 * lane]     = v0.x + v0.y;
        Part[w][o * STILE + 2 * lane + 1] = v1.x + v1.y;
    }
    __syncthreads();
    for (int e = tid; e < ODIM * STILE; e += 256) {
        float sv = 0.f;
        #pragma unroll
        for (int ww = 0; ww < 8; ww++) sv += Part[ww][e];
        Cent[e] = sv;
    }
    __syncthreads();
    if (tid < STILE) {
        const float inv32 = 1.f / 32.f;
        float sn = 0.f;
        #pragma unroll
        for (int o = 0; o < 16; o++) { float v = Cent[o * STILE + tid] * inv32; sn += v * v; }
        Fac[tid] = (sn / ((1.f + sn) * sqrtf(sn + 1e-7f))) * inv32;  // fold /32
    }
    __syncthreads();
    float fw0 = Fac[2 * lane], fw1 = Fac[2 * lane + 1];
    float2 o1[16];
    #pragma unroll
    for (int o = 0; o < 16; o++) {
        float2 cv = *(float2*)&Cent[o * STILE + 2 * lane];
        o1[o] = make_float2(cv.x * fw0, cv.y * fw1);
    }

    // ---------------- pass 2: agreement ----------------
    ((float4*)Wb[0])[tid] = Wf4[tid];
    q0 = *(const ulonglong2*)(Pw);
    q1 = *(const ulonglong2*)(Pw + SPOS);
    q2 = *(const ulonglong2*)(Pw + 2 * SPOS);
    q3 = *(const ulonglong2*)(Pw + 3 * SPOS);
    __syncthreads();

    for (int blk = 0; blk < NBLK; blk++) {
        int nb = (blk + 1 < NBLK) ? blk + 1 : 0;
        ((float4*)Wb[(blk + 1) & 1])[tid] = Wf4[nb * 256 + tid];
        const u64* Pn = g_patchP + ((size_t)(nb * 8 + w) * 4) * SPOS + sbase + 2 * lane;
        ulonglong2 n0 = *(const ulonglong2*)(Pn);
        ulonglong2 n1 = *(const ulonglong2*)(Pn + SPOS);
        ulonglong2 n2 = *(const ulonglong2*)(Pn + 2 * SPOS);
        ulonglong2 n3 = *(const ulonglong2*)(Pn + 3 * SPOS);

        const float* Wc = Wb[blk & 1] + w * 128;
        u64 ag0 = 0ULL, ag1 = 0ULL;
        #pragma unroll
        for (int o = 0; o < 16; o++) {
            const ulonglong2* wr = (const ulonglong2*)(Wc + o * 8);
            ulonglong2 w0 = wr[0], w1 = wr[1];
            u64 pr0 = 0ULL, pr1 = 0ULL;
            fma2(pr0, w0.x, q0.x); fma2(pr0, w0.y, q1.x);
            fma2(pr0, w1.x, q2.x); fma2(pr0, w1.y, q3.x);
            fma2(pr1, w0.x, q0.y); fma2(pr1, w0.y, q1.y);
            fma2(pr1, w1.x, q2.y); fma2(pr1, w1.y, q3.y);
            fma2(ag0, f2u(o1[o].x, o1[o].x), pr0);
            fma2(ag1, f2u(o1[o].y, o1[o].y), pr1);
        }
        float2 r0 = u2f(ag0), r1 = u2f(ag1);
        *(float2*)&g_agreeT[((size_t)f * CDIM + blk * 8 + w) * SPOS + sbase + 2 * lane] =
            make_float2(r0.x + r0.y, r1.x + r1.y);
        q0 = n0; q1 = n1; q2 = n2; q3 = n3;
        __syncthreads();
    }
}

// ---------------------------------------------------------------------------
// K2: softmax denominator over f per (c,s): (max, 1/sum). cc rebuilt in K3.
// ---------------------------------------------------------------------------
__global__ void k_den() {
    int j = blockIdx.x * blockDim.x + threadIdx.x;
    if (j >= CDIM * SPOS) return;
    float v[32];
    float mx = -1e30f;
    #pragma unroll
    for (int ff = 0; ff < 32; ff++) {
        v[ff] = g_agreeT[(size_t)ff * (CDIM * SPOS) + j];
        mx = fmaxf(mx, v[ff]);
    }
    float sum = 0.f;
    #pragma unroll
    for (int ff = 0; ff < 32; ff++) sum += __expf(v[ff] - mx);
    g_den[j] = make_float2(mx, 1.f / sum);
}

// ---------------------------------------------------------------------------
// K3: centroid2 = sum_c cc * preds ; squash ; out[s][f][o]
// Scalar accumulators (32 regs) so P/ag/den prefetch fits under 128 regs.
// ---------------------------------------------------------------------------
__global__ void __launch_bounds__(256, 2) k_phase3(const float* __restrict__ Wg,
                                                   float* __restrict__ out) {
    __shared__ __align__(16) float Wb[2][1024];
    __shared__ float Part[8][ODIM * STILE];
    __shared__ float Cent[ODIM * STILE];
    __shared__ float Fac[STILE];

    const int f = blockIdx.x, st = blockIdx.y;
    const int tid = threadIdx.x, w = tid >> 5, lane = tid & 31;
    const int sbase = st * STILE;
    const float4* Wf4 = (const float4*)(Wg + (size_t)f * CDIM * 128);
    const float* agf = g_agreeT + (size_t)f * (CDIM * SPOS);
    const u64* Pw = g_patchP + (size_t)w * 4 * SPOS + sbase + 2 * lane;

    float accx[16], accy[16];
    #pragma unroll
    for (int o = 0; o < 16; o++) { accx[o] = 0.f; accy[o] = 0.f; }

    ((float4*)Wb[0])[tid] = Wf4[tid];
    ulonglong2 q0 = *(const ulonglong2*)(Pw);
    ulonglong2 q1 = *(const ulonglong2*)(Pw + SPOS);
    ulonglong2 q2 = *(const ulonglong2*)(Pw + 2 * SPOS);
    ulonglong2 q3 = *(const ulonglong2*)(Pw + 3 * SPOS);
    float2 ag = *(const float2*)(agf + (size_t)w * SPOS + sbase + 2 * lane);
    float4 dv = *(const float4*)&g_den[(size_t)w * SPOS + sbase + 2 * lane];
    __syncthreads();

    for (int blk = 0; blk < NBLK; blk++) {
        int nb = (blk + 1 < NBLK) ? blk + 1 : 0;
        int cn = nb * 8 + w;
        ((float4*)Wb[(blk + 1) & 1])[tid] = Wf4[nb * 256 + tid];
        const u64* Pn = g_patchP + ((size_t)cn * 4) * SPOS + sbase + 2 * lane;
        ulonglong2 n0 = *(const ulonglong2*)(Pn);
        ulonglong2 n1 = *(const ulonglong2*)(Pn + SPOS);
        ulonglong2 n2 = *(const ulonglong2*)(Pn + 2 * SPOS);
        ulonglong2 n3 = *(const ulonglong2*)(Pn + 3 * SPOS);
        float2 agn = *(const float2*)(agf + (size_t)cn * SPOS + sbase + 2 * lane);
        float4 dvn = *(const float4*)&g_den[(size_t)cn * SPOS + sbase + 2 * lane];

        float cx = __expf(ag.x - dv.x) * dv.y;   // routing coefficient
        float cy = __expf(ag.y - dv.z) * dv.w;

        const float* Wc = Wb[blk & 1] + w * 128;
        #pragma unroll
        for (int o = 0; o < 16; o++) {
            const ulonglong2* wr = (const ulonglong2*)(Wc + o * 8);
            ulonglong2 w0 = wr[0], w1 = wr[1];
            u64 pr0 = 0ULL, pr1 = 0ULL;
            fma2(pr0, w0.x, q0.x); fma2(pr0, w0.y, q1.x);
            fma2(pr0, w1.x, q2.x); fma2(pr0, w1.y, q3.x);
            fma2(pr1, w0.x, q0.y); fma2(pr1, w0.y, q1.y);
            fma2(pr1, w1.x, q2.y); fma2(pr1, w1.y, q3.y);
            float2 p0 = u2f(pr0), p1 = u2f(pr1);
            accx[o] = fmaf(cx, p0.x + p0.y, accx[o]);
            accy[o] = fmaf(cy, p1.x + p1.y, accy[o]);
        }
        q0 = n0; q1 = n1; q2 = n2; q3 = n3;
        ag = agn; dv = dvn;
        __syncthreads();
    }

    #pragma unroll
    for (int o = 0; o < 16; o++) {
        Part[w][o * STILE + 2 * lane]     = accx[o];
        Part[w][o * STILE + 2 * lane + 1] = accy[o];
    }
    __syncthreads();
    for (int e = tid; e < ODIM * STILE; e += 256) {
        float sv = 0.f;
        #pragma unroll
        for (int ww = 0; ww < 8; ww++) sv += Part[ww][e];
        Cent[e] = sv;
    }
    __syncthreads();
    if (tid < STILE) {
        float sn = 0.f;
        #pragma unroll
        for (int o = 0; o < 16; o++) { float v = Cent[o * STILE + tid]; sn += v * v; }
        Fac[tid] = sn / ((1.f + sn) * sqrtf(sn + 1e-7f));
    }
    __syncthreads();
    {
        int s = tid >> 2, oq = tid & 3;    // 64 s x 4 o-quads
        float fs = Fac[s];
        float4 r;
        r.x = Cent[(oq * 4 + 0) * STILE + s] * fs;
        r.y = Cent[(oq * 4 + 1) * STILE + s] * fs;
        r.z = Cent[(oq * 4 + 2) * STILE + s] * fs;
        r.w = Cent[(oq * 4 + 3) * STILE + s] * fs;
        *(float4*)(out + ((size_t)(sbase + s) * FDIM + f) * ODIM + oq * 4) = r;
    }
}

// ---------------------------------------------------------------------------
extern "C" void kernel_launch(void* const* d_in, const int* in_sizes, int n_in,
                              void* d_out, int out_size) {
    const float* x  = (const float*)d_in[0];
    const float* Wg = (const float*)d_in[1];
    if (n_in >= 2 && in_sizes[0] == 1179648) { const float* t = x; x = Wg; Wg = t; }
    float* out = (float*)d_out;

    k_extract<<<(CDIM * SPOS + 255) / 256, 256>>>(x);
    dim3 g(FDIM, NST);   // (32, 9) = 288 CTAs, 2 CTAs/SM
    k_phase1<<<g, 256>>>(Wg);
    k_den<<<(CDIM * SPOS + 255) / 256, 256>>>();
    k_phase3<<<g, 256>>>(Wg, out);
}